// round 8
// baseline (speedup 1.0000x reference)
#include <cuda_runtime.h>
#include <cuda_fp16.h>
#include <cuda_bf16.h>
#include <cstdint>
#include <cstddef>

#define BB 4096
#define NN 8192
#define DD 256

// ---- gemm1 tiling (fp16) ----
#define MT      64
#define KSPLIT  4
#define KPER    (NN / KSPLIT)     // 2048
#define KC      64
#define NCHUNK  (KPER / KC)       // 32
#define A_BYTES (64 * 128)
#define B_BYTES (64 * 512)
#define STG     (A_BYTES + B_BYTES)

// ---- mlp smem ----
#define MLP_IN_PL (128 * 512)
#define MLP_W_PL  (64 * 512)
#define FUSE_SMEM (2 * MLP_IN_PL + 2 * MLP_W_PL)  // 196608 (>= 3*STG)

// ---- prep dispatch ----
#define PREP_SORT   0
#define PREP_CONVA  1
#define PREP_CONVE  (PREP_CONVA + BB)
#define PREP_CONVW  (PREP_CONVE + (NN * DD) / 1024)
#define PREP_GRID   (PREP_CONVW + (3 * DD * DD) / 1024)

#define FUSE_GRID   128
#define FUSE_THREADS 512

// -------------------- device scratch --------------------
__device__ __align__(256) int   g_labels_s[BB];
__device__ __align__(256) int   g_idx_s[BB];
__device__ __align__(256) int   g_perm[BB];
__device__ int   g_total;
__device__ unsigned g_arrive;    // monotone grid-barrier counter (never reset)
__device__ unsigned g_work;      // gemm1 work queue (reset by prep each launch)
__device__ __align__(256) float g_rsumF[BB];
__device__ __align__(256) __half g_Ah[(size_t)BB * NN];
__device__ __align__(256) __half g_Eh[(size_t)NN * DD];
__device__ __align__(256) __nv_bfloat16 g_WHi[3 * DD * DD];
__device__ __align__(256) __nv_bfloat16 g_WLo[3 * DD * DD];
__device__ __align__(256) __nv_bfloat16 g_hHi[BB * DD];
__device__ __align__(256) __nv_bfloat16 g_hLo[BB * DD];
__device__ __align__(256) __nv_bfloat16 g_h2Hi[BB * DD];
__device__ __align__(256) __nv_bfloat16 g_h2Lo[BB * DD];
__device__ __align__(256) float g_part[(size_t)KSPLIT * BB * DD];

// -------------------- helpers --------------------
__device__ __forceinline__ uint32_t smem_u32(const void* p) {
    uint32_t a;
    asm("{ .reg .u64 t; cvta.to.shared.u64 t, %1; cvt.u32.u64 %0, t; }" : "=r"(a) : "l"(p));
    return a;
}
#define CP16(dst, src) \
    asm volatile("cp.async.cg.shared.global [%0], [%1], 16;" \
        :: "r"(dst), "l"(__cvta_generic_to_global(src)) : "memory")
#define CP_COMMIT() asm volatile("cp.async.commit_group;" ::: "memory")

#define LDSM_X4(r0, r1, r2, r3, addr) \
    asm volatile("ldmatrix.sync.aligned.m8n8.x4.shared.b16 {%0,%1,%2,%3}, [%4];" \
        : "=r"(r0), "=r"(r1), "=r"(r2), "=r"(r3) : "r"(addr))
#define LDSM_X4_T(r0, r1, r2, r3, addr) \
    asm volatile("ldmatrix.sync.aligned.m8n8.x4.trans.shared.b16 {%0,%1,%2,%3}, [%4];" \
        : "=r"(r0), "=r"(r1), "=r"(r2), "=r"(r3) : "r"(addr))

#define MMA_F16(d, a0, a1, a2, a3, b0, b1) \
    asm volatile("mma.sync.aligned.m16n8k16.row.col.f32.f16.f16.f32 " \
        "{%0,%1,%2,%3}, {%4,%5,%6,%7}, {%8,%9}, {%0,%1,%2,%3};" \
        : "+f"((d)[0]), "+f"((d)[1]), "+f"((d)[2]), "+f"((d)[3]) \
        : "r"(a0), "r"(a1), "r"(a2), "r"(a3), "r"(b0), "r"(b1))

#define MMA_BF16(d, a0, a1, a2, a3, b0, b1) \
    asm volatile("mma.sync.aligned.m16n8k16.row.col.f32.bf16.bf16.f32 " \
        "{%0,%1,%2,%3}, {%4,%5,%6,%7}, {%8,%9}, {%0,%1,%2,%3};" \
        : "+f"((d)[0]), "+f"((d)[1]), "+f"((d)[2]), "+f"((d)[3]) \
        : "r"(a0), "r"(a1), "r"(a2), "r"(a3), "r"(b0), "r"(b1))

// Monotone grid barrier: works across CUDA-graph replays without reset
// (counter only ever crosses multiples of gridDim).
__device__ __forceinline__ void grid_barrier() {
    __syncthreads();
    if (threadIdx.x == 0) {
        __threadfence();
        unsigned v = atomicAdd(&g_arrive, 1u) + 1u;
        unsigned goal = ((v + FUSE_GRID - 1u) / FUSE_GRID) * FUSE_GRID;
        while (*((volatile unsigned*)&g_arrive) < goal) { }
        __threadfence();
    }
    __syncthreads();
}

// ==================== 1) fused prep: sort + convA + convE + convW ====================
__global__ void __launch_bounds__(256) prep_kernel(
    const int* __restrict__ labels, const int* __restrict__ nidx,
    const float* __restrict__ A,    const float* __restrict__ E,
    const float* __restrict__ W,    float* __restrict__ out_labels) {
    const int bid = blockIdx.x;
    const int t   = threadIdx.x;

    if (bid == PREP_SORT) {
        __shared__ int sc[256];
        int g0 = t * 16;
        int lab[16], nd[16];
        int c = 0;
#pragma unroll
        for (int j = 0; j < 16; j++) {
            lab[j] = labels[g0 + j];
            nd[j]  = nidx[g0 + j];
            c += (lab[j] != 0);
        }
        sc[t] = c;
        __syncthreads();
        for (int off = 1; off < 256; off <<= 1) {
            int v = sc[t];
            int add = (t >= off) ? sc[t - off] : 0;
            __syncthreads();
            sc[t] = v + add;
            __syncthreads();
        }
        int total = sc[255];
        int p     = sc[t] - c;
        if (t == 0) { g_total = total; g_work = 0u; }
#pragma unroll
        for (int j = 0; j < 16; j++) {
            int g = g0 + j;
            int dst;
            if (lab[j]) { dst = p; p++; }
            else        { dst = total + (g - p); }
            g_labels_s[dst] = lab[j];
            g_idx_s[dst]    = nd[j];
            g_perm[dst]     = g;
            if (out_labels) out_labels[dst] = (float)lab[j];
        }
    } else if (bid < PREP_CONVE) {
        const int b = bid - PREP_CONVA;
        if (labels[b] == 0) return;
        const int node = nidx[b];
        const float* src = A + (size_t)node * NN;
        __half* dst = g_Ah + (size_t)b * NN;
        float s = 0.f;
#pragma unroll
        for (int i = 0; i < 8; i++) {
            size_t idx = (size_t)t * 4 + (size_t)i * 1024;
            float4 v = *reinterpret_cast<const float4*>(src + idx);
            __half2 h0 = __float22half2_rn(make_float2(v.x, v.y));
            __half2 h1 = __float22half2_rn(make_float2(v.z, v.w));
            __half2* d = reinterpret_cast<__half2*>(dst + idx);
            d[0] = h0; d[1] = h1;
            float2 f0 = __half22float2(h0), f1 = __half22float2(h1);
            s += (f0.x + f0.y) + (f1.x + f1.y);
        }
#pragma unroll
        for (int off = 16; off > 0; off >>= 1)
            s += __shfl_down_sync(0xffffffffu, s, off);
        __shared__ float ws[8];
        if ((t & 31) == 0) ws[t >> 5] = s;
        __syncthreads();
        if (t == 0) {
            float tot = 0.f;
#pragma unroll
            for (int w = 0; w < 8; w++) tot += ws[w];
            g_rsumF[b] = tot;
        }
    } else if (bid < PREP_CONVW) {
        size_t i = (size_t)(bid - PREP_CONVE) * 1024 + t * 4;
        float4 v = *reinterpret_cast<const float4*>(E + i);
        __half2* dst = reinterpret_cast<__half2*>(g_Eh + i);
        dst[0] = __float22half2_rn(make_float2(v.x, v.y));
        dst[1] = __float22half2_rn(make_float2(v.z, v.w));
    } else {
        size_t i = (size_t)(bid - PREP_CONVW) * 1024 + t * 4;
        float4 v = *reinterpret_cast<const float4*>(W + i);
        float f[4] = {v.x, v.y, v.z, v.w};
#pragma unroll
        for (int j = 0; j < 4; j++) {
            __nv_bfloat16 hi = __float2bfloat16_rn(f[j]);
            __nv_bfloat16 lo = __float2bfloat16_rn(f[j] - __bfloat162float(hi));
            g_WHi[i + j] = hi;
            g_WLo[i + j] = lo;
        }
    }
}

// ==================== gemm1 tile (512 threads, 16 warps) ====================
__device__ __forceinline__ void gemm1_tile(uint32_t sb, int kb, int m0) {
    const int t = threadIdx.x, lane = t & 31, wid = t >> 5;
    const int wm = wid & 3, wn = wid >> 2;    // wn 0..3 (64-col bands)
    const size_t kBase = (size_t)kb * KPER;
    const int mA = t >> 3, s8 = t & 7;
    const __half* rowA = g_Ah + (size_t)g_perm[m0 + mA] * NN;

    float acc[8][4];
#pragma unroll
    for (int f = 0; f < 8; f++)
#pragma unroll
        for (int r = 0; r < 4; r++) acc[f][r] = 0.f;

    auto load_stage = [&](int c) {
        const uint32_t base = sb + (uint32_t)((c % 3) * STG);
        const size_t kOff = kBase + (size_t)c * KC;
        CP16(base + mA * 128 + (uint32_t)((s8 * 16) ^ ((mA & 7) << 4)),
             rowA + kOff + s8 * 8);
#pragma unroll
        for (int i = 0; i < 4; i++) {
            int g = t + 512 * i;
            int k = g >> 5, ns = g & 31;
            uint32_t dst = base + A_BYTES + k * 512 + (uint32_t)((ns * 16) ^ ((k & 7) << 4));
            CP16(dst, g_Eh + (kOff + k) * DD + ns * 8);
        }
    };

    auto compute_stage = [&](int c) {
        const uint32_t Ab = sb + (uint32_t)((c % 3) * STG);
        const uint32_t Bb = Ab + A_BYTES;
        const int q = lane >> 3, l7 = lane & 7;
#pragma unroll
        for (int ks = 0; ks < 4; ks++) {
            const int am  = wm * 16 + (q & 1) * 8 + l7;
            const int akB = ks * 32 + (q >> 1) * 16;
            uint32_t a0, a1, a2, a3;
            LDSM_X4(a0, a1, a2, a3, Ab + am * 128 + (uint32_t)(akB ^ ((am & 7) << 4)));
            const int bk = ks * 16 + (q & 1) * 8 + l7;
            const uint32_t brow = Bb + bk * 512;
            const uint32_t bxor = (uint32_t)((bk & 7) << 4);
#pragma unroll
            for (int jb = 0; jb < 4; jb++) {
                const uint32_t nB = (uint32_t)((wn * 64 + jb * 16 + (q >> 1) * 8) * 2);
                uint32_t b0, b1, b2, b3;
                LDSM_X4_T(b0, b1, b2, b3, brow + (nB ^ bxor));
                MMA_F16(acc[jb * 2],     a0, a1, a2, a3, b0, b1);
                MMA_F16(acc[jb * 2 + 1], a0, a1, a2, a3, b2, b3);
            }
        }
    };

    load_stage(0); CP_COMMIT();
    load_stage(1); CP_COMMIT();
    load_stage(2); CP_COMMIT();
    for (int c = 0; c < NCHUNK; c++) {
        asm volatile("cp.async.wait_group 2;" ::: "memory");
        __syncthreads();
        compute_stage(c);
        __syncthreads();
        if (c + 3 < NCHUNK) load_stage(c + 3);
        CP_COMMIT();
    }

    float* pbase = g_part + ((size_t)kb * BB + m0) * DD;
    const int row = wm * 16 + (lane >> 2);
    const int cb  = wn * 64 + (lane & 3) * 2;
#pragma unroll
    for (int f = 0; f < 8; f++) {
        const int n = cb + f * 8;
        *reinterpret_cast<float2*>(pbase + (size_t)row * DD + n) =
            make_float2(acc[f][0], acc[f][1]);
        *reinterpret_cast<float2*>(pbase + (size_t)(row + 8) * DD + n) =
            make_float2(acc[f][2], acc[f][3]);
    }
}

// ==================== MLP layer (512 threads, 16 warps) ====================
__device__ __forceinline__ void mlp_layer(
    uint32_t sb,
    const __nv_bfloat16* __restrict__ inHi, const __nv_bfloat16* __restrict__ inLo,
    const __nv_bfloat16* __restrict__ WHi,  const __nv_bfloat16* __restrict__ WLo,
    const float* __restrict__ bias,
    __nv_bfloat16* __restrict__ outHi, __nv_bfloat16* __restrict__ outLo,
    float* __restrict__ outF, int i0, int o0) {
    const int t = threadIdx.x, lane = t & 31, wid = t >> 5;
    const int wm = wid & 7, wn = wid >> 3;   // 16 rows x 32 cols per warp
    const uint32_t sINhi = sb;
    const uint32_t sINlo = sb + MLP_IN_PL;
    const uint32_t sWhi  = sb + 2 * MLP_IN_PL;
    const uint32_t sWlo  = sWhi + MLP_W_PL;

    auto load_half = [&](int h) {
#pragma unroll
        for (int i = 0; i < 4; i++) {
            int g = t + 512 * i;
            int m = g >> 4, s = (g & 15) + h * 16;
            uint32_t off = m * 512 + (uint32_t)((s * 16) ^ ((m & 7) << 4));
            CP16(sINhi + off, inHi + (size_t)(i0 + m) * DD + s * 8);
            CP16(sINlo + off, inLo + (size_t)(i0 + m) * DD + s * 8);
        }
#pragma unroll
        for (int i = 0; i < 2; i++) {
            int g = t + 512 * i;
            int n = g >> 4, s = (g & 15) + h * 16;
            uint32_t off = n * 512 + (uint32_t)((s * 16) ^ ((n & 7) << 4));
            CP16(sWhi + off, WHi + (size_t)(o0 + n) * DD + s * 8);
            CP16(sWlo + off, WLo + (size_t)(o0 + n) * DD + s * 8);
        }
    };

    float acc[4][4];
#pragma unroll
    for (int f = 0; f < 4; f++)
#pragma unroll
        for (int r = 0; r < 4; r++) acc[f][r] = 0.f;

    auto comp_half = [&](int h) {
        const int q = lane >> 3, l7 = lane & 7;
#pragma unroll
        for (int ksl = 0; ksl < 8; ksl++) {
            const int ks = h * 8 + ksl;
            uint32_t ah[4], al[4];
            {
                const int m  = wm * 16 + (q & 1) * 8 + l7;
                const int kB = ks * 32 + (q >> 1) * 16;
                const uint32_t off = m * 512 + (uint32_t)(kB ^ ((m & 7) << 4));
                LDSM_X4(ah[0], ah[1], ah[2], ah[3], sINhi + off);
                LDSM_X4(al[0], al[1], al[2], al[3], sINlo + off);
            }
            uint32_t bh[2][4], bl[2][4];
#pragma unroll
            for (int nn = 0; nn < 2; nn++) {
                const int n  = wn * 32 + nn * 16 + (q >> 1) * 8 + l7;
                const int kB = ks * 32 + (q & 1) * 16;
                const uint32_t off = n * 512 + (uint32_t)(kB ^ ((n & 7) << 4));
                LDSM_X4(bh[nn][0], bh[nn][1], bh[nn][2], bh[nn][3], sWhi + off);
                LDSM_X4(bl[nn][0], bl[nn][1], bl[nn][2], bl[nn][3], sWlo + off);
            }
#pragma unroll
            for (int nn = 0; nn < 2; nn++) {
                float* d0 = acc[nn * 2];
                float* d1 = acc[nn * 2 + 1];
                MMA_BF16(d0, ah[0], ah[1], ah[2], ah[3], bh[nn][0], bh[nn][1]);
                MMA_BF16(d0, al[0], al[1], al[2], al[3], bh[nn][0], bh[nn][1]);
                MMA_BF16(d0, ah[0], ah[1], ah[2], ah[3], bl[nn][0], bl[nn][1]);
                MMA_BF16(d1, ah[0], ah[1], ah[2], ah[3], bh[nn][2], bh[nn][3]);
                MMA_BF16(d1, al[0], al[1], al[2], al[3], bh[nn][2], bh[nn][3]);
                MMA_BF16(d1, ah[0], ah[1], ah[2], ah[3], bl[nn][2], bl[nn][3]);
            }
        }
    };

    load_half(0); CP_COMMIT();
    load_half(1); CP_COMMIT();
    asm volatile("cp.async.wait_group 1;" ::: "memory");
    __syncthreads();
    comp_half(0);
    asm volatile("cp.async.wait_group 0;" ::: "memory");
    __syncthreads();
    comp_half(1);

    const int row0 = i0 + wm * 16 + (lane >> 2);
#pragma unroll
    for (int f = 0; f < 4; f++) {
        const int col = o0 + wn * 32 + f * 8 + (lane & 3) * 2;
        const float b0 = bias[col], b1 = bias[col + 1];
        float y00 = fmaxf(acc[f][0] + b0, 0.f);
        float y01 = fmaxf(acc[f][1] + b1, 0.f);
        float y10 = fmaxf(acc[f][2] + b0, 0.f);
        float y11 = fmaxf(acc[f][3] + b1, 0.f);
        if (outF) {
            *reinterpret_cast<float2*>(outF + (size_t)row0 * DD + col) = make_float2(y00, y01);
            *reinterpret_cast<float2*>(outF + (size_t)(row0 + 8) * DD + col) = make_float2(y10, y11);
        } else {
            float y[4] = {y00, y01, y10, y11};
            __nv_bfloat16 hi[4], lo[4];
#pragma unroll
            for (int j = 0; j < 4; j++) {
                hi[j] = __float2bfloat16_rn(y[j]);
                lo[j] = __float2bfloat16_rn(y[j] - __bfloat162float(hi[j]));
            }
            *reinterpret_cast<__nv_bfloat162*>(outHi + (size_t)row0 * DD + col) = __halves2bfloat162(hi[0], hi[1]);
            *reinterpret_cast<__nv_bfloat162*>(outHi + (size_t)(row0 + 8) * DD + col) = __halves2bfloat162(hi[2], hi[3]);
            *reinterpret_cast<__nv_bfloat162*>(outLo + (size_t)row0 * DD + col) = __halves2bfloat162(lo[0], lo[1]);
            *reinterpret_cast<__nv_bfloat162*>(outLo + (size_t)(row0 + 8) * DD + col) = __halves2bfloat162(lo[2], lo[3]);
        }
    }
}

// ==================== 2) fused persistent kernel: gemm1 + finalize + 3x MLP ====================
__global__ void __launch_bounds__(FUSE_THREADS, 1) fused_kernel(
    const float* __restrict__ E, const float* __restrict__ bias,
    float* __restrict__ out_h) {
    extern __shared__ __align__(1024) char smem[];
    const uint32_t sb = smem_u32(smem);
    const int c = blockIdx.x;
    const int t = threadIdx.x;
    __shared__ int s_item;

    // ---- phase G: gemm1 over work queue ----
    const int nItems = KSPLIT * ((g_total + MT - 1) / MT);
    for (;;) {
        if (t == 0) s_item = (int)atomicAdd(&g_work, 1u);
        __syncthreads();
        const int item = s_item;
        __syncthreads();
        if (item >= nItems) break;
        gemm1_tile(sb, item & (KSPLIT - 1), (item / KSPLIT) * MT);
    }
    grid_barrier();

    // ---- phase F: finalize (reduce ksplits, normalize, gather, bf16-split) ----
    {
        const int b   = c * 32 + (t >> 4);
        const int sub = t & 15;              // 16 elems per thread
        const int lab  = g_labels_s[b];
        const int node = g_idx_s[b];
        float v[16];
        if (lab) {
            const float inv = 1.0f / g_rsumF[g_perm[b]];
#pragma unroll
            for (int e = 0; e < 4; e++) {
                float4 acc4 = make_float4(0.f, 0.f, 0.f, 0.f);
#pragma unroll
                for (int kb = 0; kb < KSPLIT; kb++) {
                    float4 p = *reinterpret_cast<const float4*>(
                        g_part + ((size_t)kb * BB + b) * DD + sub * 16 + e * 4);
                    acc4.x += p.x; acc4.y += p.y; acc4.z += p.z; acc4.w += p.w;
                }
                v[e * 4 + 0] = acc4.x * inv;
                v[e * 4 + 1] = acc4.y * inv;
                v[e * 4 + 2] = acc4.z * inv;
                v[e * 4 + 3] = acc4.w * inv;
            }
        } else {
#pragma unroll
            for (int e = 0; e < 4; e++) {
                float4 p = *reinterpret_cast<const float4*>(
                    E + (size_t)node * DD + sub * 16 + e * 4);
                v[e * 4 + 0] = p.x; v[e * 4 + 1] = p.y;
                v[e * 4 + 2] = p.z; v[e * 4 + 3] = p.w;
            }
        }
        const size_t o = (size_t)b * DD + sub * 16;
#pragma unroll
        for (int j = 0; j < 16; j += 2) {
            __nv_bfloat16 h0 = __float2bfloat16_rn(v[j]);
            __nv_bfloat16 h1 = __float2bfloat16_rn(v[j + 1]);
            __nv_bfloat16 l0 = __float2bfloat16_rn(v[j]     - __bfloat162float(h0));
            __nv_bfloat16 l1 = __float2bfloat16_rn(v[j + 1] - __bfloat162float(h1));
            *reinterpret_cast<__nv_bfloat162*>(g_hHi + o + j) = __halves2bfloat162(h0, h1);
            *reinterpret_cast<__nv_bfloat162*>(g_hLo + o + j) = __halves2bfloat162(l0, l1);
        }
    }
    grid_barrier();

    // ---- phases 1-3: MLP layers ----
    const int i0 = (c & 31) * 128;
    const int o0 = (c >> 5) * 64;
    mlp_layer(sb, g_hHi, g_hLo, g_WHi, g_WLo, bias, g_h2Hi, g_h2Lo, nullptr, i0, o0);
    grid_barrier();
    mlp_layer(sb, g_h2Hi, g_h2Lo, g_WHi + DD * DD, g_WLo + DD * DD, bias + DD,
              g_hHi, g_hLo, nullptr, i0, o0);
    grid_barrier();
    mlp_layer(sb, g_hHi, g_hLo, g_WHi + 2 * DD * DD, g_WLo + 2 * DD * DD, bias + 2 * DD,
              nullptr, nullptr, out_h, i0, o0);
}

// ==================== launch ====================
extern "C" void kernel_launch(void* const* d_in, const int* in_sizes, int n_in,
                              void* d_out, int out_size) {
    const int*   labels = (const int*)d_in[0];
    const int*   nidx   = (const int*)d_in[1];
    const float* A      = (const float*)d_in[2];
    const float* E      = (const float*)d_in[3];
    const float* W      = (const float*)d_in[4];
    const float* bias   = (const float*)d_in[5];

    float* out        = (float*)d_out;
    float* out_labels = nullptr;
    float* out_h      = out;
    if (out_size >= BB * DD + BB) {
        out_labels = out;
        out_h      = out + BB;
    }

    cudaFuncSetAttribute(fused_kernel,
                         cudaFuncAttributeMaxDynamicSharedMemorySize, FUSE_SMEM);

    prep_kernel<<<PREP_GRID, 256>>>(labels, nidx, A, E, W, out_labels);
    fused_kernel<<<FUSE_GRID, FUSE_THREADS, FUSE_SMEM>>>(E, bias, out_h);
}

// round 9
// speedup vs baseline: 1.4048x; 1.4048x over previous
#include <cuda_runtime.h>
#include <cuda_fp16.h>
#include <cuda_bf16.h>
#include <cstdint>
#include <cstddef>

#define BB 4096
#define NN 8192
#define DD 256

// ---- gemm1 tiling (fp16) ----
#define MT      64
#define KSPLIT  4
#define KPER    (NN / KSPLIT)     // 2048
#define KC      64
#define NCHUNK  (KPER / KC)       // 32
#define A_BYTES (64 * 128)        // 64 m-rows x 64 fp16
#define B_BYTES (256 * 128)       // 256 n-rows x 64 fp16
#define STG     (A_BYTES + B_BYTES)
#define GEMM_SMEM (3 * STG)       // 122880

// ---- mlp smem ----
#define MLP_IN_PL (128 * 512)
#define MLP_W_PL  (64 * 512)
#define MLP_SMEM  (2 * MLP_IN_PL + 2 * MLP_W_PL)  // 196608

// ---- prep dispatch ----
#define PREP_SORT   0
#define PREP_CONVA  1                          // BB blocks
#define PREP_CONVE  (PREP_CONVA + BB)          // 512 blocks (64x64 transpose tiles)
#define PREP_CONVW  (PREP_CONVE + (NN / 64) * (DD / 64))
#define PREP_GRID   (PREP_CONVW + (3 * DD * DD) / 1024)

// -------------------- device scratch --------------------
__device__ __align__(256) int   g_labels_s[BB];
__device__ __align__(256) int   g_idx_s[BB];
__device__ __align__(256) int   g_perm[BB];
__device__ int   g_total;
__device__ __align__(256) float g_rsumF[BB];
__device__ __align__(256) __half g_Ah[(size_t)BB * NN];    // by ORIGINAL batch idx
__device__ __align__(256) __half g_EhT[(size_t)DD * NN];   // E transposed [n][k], fp16
__device__ __align__(256) __nv_bfloat16 g_WHi[3 * DD * DD];
__device__ __align__(256) __nv_bfloat16 g_WLo[3 * DD * DD];
__device__ __align__(256) __nv_bfloat16 g_hHi[BB * DD];
__device__ __align__(256) __nv_bfloat16 g_hLo[BB * DD];
__device__ __align__(256) __nv_bfloat16 g_h2Hi[BB * DD];
__device__ __align__(256) __nv_bfloat16 g_h2Lo[BB * DD];
__device__ __align__(256) float g_part[(size_t)KSPLIT * BB * DD];

// -------------------- helpers --------------------
__device__ __forceinline__ uint32_t smem_u32(const void* p) {
    uint32_t a;
    asm("{ .reg .u64 t; cvta.to.shared.u64 t, %1; cvt.u32.u64 %0, t; }" : "=r"(a) : "l"(p));
    return a;
}
#define CP16(dst, src) \
    asm volatile("cp.async.cg.shared.global [%0], [%1], 16;" \
        :: "r"(dst), "l"(__cvta_generic_to_global(src)) : "memory")
#define CP_COMMIT() asm volatile("cp.async.commit_group;" ::: "memory")

#define LDSM_X4(r0, r1, r2, r3, addr) \
    asm volatile("ldmatrix.sync.aligned.m8n8.x4.shared.b16 {%0,%1,%2,%3}, [%4];" \
        : "=r"(r0), "=r"(r1), "=r"(r2), "=r"(r3) : "r"(addr))

#define MMA_F16(d, a0, a1, a2, a3, b0, b1) \
    asm volatile("mma.sync.aligned.m16n8k16.row.col.f32.f16.f16.f32 " \
        "{%0,%1,%2,%3}, {%4,%5,%6,%7}, {%8,%9}, {%0,%1,%2,%3};" \
        : "+f"((d)[0]), "+f"((d)[1]), "+f"((d)[2]), "+f"((d)[3]) \
        : "r"(a0), "r"(a1), "r"(a2), "r"(a3), "r"(b0), "r"(b1))

#define MMA_BF16(d, a0, a1, a2, a3, b0, b1) \
    asm volatile("mma.sync.aligned.m16n8k16.row.col.f32.bf16.bf16.f32 " \
        "{%0,%1,%2,%3}, {%4,%5,%6,%7}, {%8,%9}, {%0,%1,%2,%3};" \
        : "+f"((d)[0]), "+f"((d)[1]), "+f"((d)[2]), "+f"((d)[3]) \
        : "r"(a0), "r"(a1), "r"(a2), "r"(a3), "r"(b0), "r"(b1))

// ==================== 1) fused prep: sort + convA + convE^T + convW ====================
__global__ void __launch_bounds__(256) prep_kernel(
    const int* __restrict__ labels, const int* __restrict__ nidx,
    const float* __restrict__ A,    const float* __restrict__ E,
    const float* __restrict__ W,    float* __restrict__ out_labels) {
    const int bid = blockIdx.x;
    const int t   = threadIdx.x;

    if (bid == PREP_SORT) {
        __shared__ int sc[256];
        int g0 = t * 16;
        int lab[16], nd[16];
        int c = 0;
#pragma unroll
        for (int j = 0; j < 16; j++) {
            lab[j] = labels[g0 + j];
            nd[j]  = nidx[g0 + j];
            c += (lab[j] != 0);
        }
        sc[t] = c;
        __syncthreads();
        for (int off = 1; off < 256; off <<= 1) {
            int v = sc[t];
            int add = (t >= off) ? sc[t - off] : 0;
            __syncthreads();
            sc[t] = v + add;
            __syncthreads();
        }
        int total = sc[255];
        int p     = sc[t] - c;
        if (t == 0) g_total = total;
#pragma unroll
        for (int j = 0; j < 16; j++) {
            int g = g0 + j;
            int dst;
            if (lab[j]) { dst = p; p++; }
            else        { dst = total + (g - p); }
            g_labels_s[dst] = lab[j];
            g_idx_s[dst]    = nd[j];
            g_perm[dst]     = g;
            if (out_labels) out_labels[dst] = (float)lab[j];
        }
    } else if (bid < PREP_CONVE) {
        // ---- convA: gather positive A rows -> fp16 + exact rounded rowsum ----
        const int b = bid - PREP_CONVA;
        if (labels[b] == 0) return;
        const int node = nidx[b];
        const float* src = A + (size_t)node * NN;
        __half* dst = g_Ah + (size_t)b * NN;
        float s = 0.f;
#pragma unroll
        for (int i = 0; i < 8; i++) {
            size_t idx = (size_t)t * 4 + (size_t)i * 1024;
            float4 v = *reinterpret_cast<const float4*>(src + idx);
            __half2 h0 = __float22half2_rn(make_float2(v.x, v.y));
            __half2 h1 = __float22half2_rn(make_float2(v.z, v.w));
            __half2* d = reinterpret_cast<__half2*>(dst + idx);
            d[0] = h0; d[1] = h1;
            float2 f0 = __half22float2(h0), f1 = __half22float2(h1);
            s += (f0.x + f0.y) + (f1.x + f1.y);
        }
#pragma unroll
        for (int off = 16; off > 0; off >>= 1)
            s += __shfl_down_sync(0xffffffffu, s, off);
        __shared__ float ws[8];
        if ((t & 31) == 0) ws[t >> 5] = s;
        __syncthreads();
        if (t == 0) {
            float tot = 0.f;
#pragma unroll
            for (int w = 0; w < 8; w++) tot += ws[w];
            g_rsumF[b] = tot;
        }
    } else if (bid < PREP_CONVW) {
        // ---- convE^T: E[k][n] -> g_EhT[n][k] fp16, 64x64 tile ----
        __shared__ float tile[64][65];
        const int b2 = bid - PREP_CONVE;
        const int k0 = (b2 >> 2) * 64;     // 128 k-tiles
        const int n0 = (b2 & 3) * 64;      // 4 n-tiles
#pragma unroll
        for (int i = 0; i < 16; i++) {
            int idx = t + 256 * i;
            int kl = idx >> 6, nl = idx & 63;
            tile[kl][nl] = E[(size_t)(k0 + kl) * DD + n0 + nl];
        }
        __syncthreads();
        const int nl = t >> 2;             // 0..63
        const int ks = (t & 3) * 16;       // 16 k per thread
        __half h[16];
#pragma unroll
        for (int j = 0; j < 16; j++)
            h[j] = __float2half_rn(tile[ks + j][nl]);
        uint4* dst = reinterpret_cast<uint4*>(g_EhT + (size_t)(n0 + nl) * NN + k0 + ks);
        dst[0] = *reinterpret_cast<uint4*>(h);
        dst[1] = *reinterpret_cast<uint4*>(h + 8);
    } else {
        // ---- convW: W -> bf16 hi/lo ----
        size_t i = (size_t)(bid - PREP_CONVW) * 1024 + t * 4;
        float4 v = *reinterpret_cast<const float4*>(W + i);
        float f[4] = {v.x, v.y, v.z, v.w};
#pragma unroll
        for (int j = 0; j < 4; j++) {
            __nv_bfloat16 hi = __float2bfloat16_rn(f[j]);
            __nv_bfloat16 lo = __float2bfloat16_rn(f[j] - __bfloat162float(hi));
            g_WHi[i + j] = hi;
            g_WLo[i + j] = lo;
        }
    }
}

// ==================== 2) fp16 tensor GEMM (E^T n-major, non-trans ldsm) ====================
// grid (KSPLIT, BB/MT), 256 threads: kb fast axis -> active tiles pack wave 1.
__global__ void __launch_bounds__(256, 1) gemm1_kernel() {
    const int kb = blockIdx.x;
    const int m0 = blockIdx.y * MT;
    if (m0 >= g_total) return;

    extern __shared__ __align__(1024) char smem[];
    const uint32_t sb = smem_u32(smem);
    const int t = threadIdx.x, lane = t & 31, wid = t >> 5;
    const int wm = wid & 3, wn = wid >> 2;      // wn 0..1 (128-col bands)
    const size_t kBase = (size_t)kb * KPER;

    const int mA = t >> 3, s8 = t & 7;
    const __half* rowA = g_Ah + (size_t)g_perm[m0 + mA] * NN;

    float acc[16][4];
#pragma unroll
    for (int f = 0; f < 16; f++)
#pragma unroll
        for (int r = 0; r < 4; r++) acc[f][r] = 0.f;

    auto load_stage = [&](int c) {
        const uint32_t base = sb + (uint32_t)((c % 3) * STG);
        const size_t kOff = kBase + (size_t)c * KC;
        // A: 64 m-rows x 128B (512 granules)
        CP16(base + mA * 128 + (uint32_t)((s8 * 16) ^ ((mA & 7) << 4)),
             rowA + kOff + s8 * 8);
        {
            const int m1 = mA + 32;
            const __half* rowA1 = g_Ah + (size_t)g_perm[m0 + m1] * NN;
            // NOTE: mA covers 0..31 with t>>3? t in 0..255 -> mA 0..31. Load both halves.
            CP16(base + m1 * 128 + (uint32_t)((s8 * 16) ^ ((m1 & 7) << 4)),
                 rowA1 + kOff + s8 * 8);
        }
        // B: 256 n-rows x 128B (2048 granules)
#pragma unroll
        for (int i = 0; i < 8; i++) {
            int g = t + 256 * i;
            int n = g >> 3, sB = g & 7;
            uint32_t dst = base + A_BYTES + n * 128 + (uint32_t)((sB * 16) ^ ((n & 7) << 4));
            CP16(dst, g_EhT + (size_t)n * NN + kOff + sB * 8);
        }
    };

    auto compute_stage = [&](int c) {
        const uint32_t Ab = sb + (uint32_t)((c % 3) * STG);
        const uint32_t Bb = Ab + A_BYTES;
        const int q = lane >> 3, l7 = lane & 7;
        const int bnr  = wn * 128 + ((lane >> 4) << 3) + l7;  // n row for ldsm
        const int bkoff = ((lane >> 3) & 1) * 16;             // k byte offset (k or k+8)
#pragma unroll
        for (int ks = 0; ks < 4; ks++) {                      // k16 steps
            const int am  = wm * 16 + (q & 1) * 8 + l7;
            const int akB = ks * 32 + (q >> 1) * 16;
            uint32_t a0, a1, a2, a3;
            LDSM_X4(a0, a1, a2, a3, Ab + am * 128 + (uint32_t)(akB ^ ((am & 7) << 4)));
            const int kbB = ks * 32 + bkoff;
#pragma unroll
            for (int jb = 0; jb < 8; jb++) {
                const int nrow = bnr + jb * 16;
                uint32_t b0, b1, b2, b3;
                LDSM_X4(b0, b1, b2, b3,
                        Bb + nrow * 128 + (uint32_t)(kbB ^ ((nrow & 7) << 4)));
                MMA_F16(acc[jb * 2],     a0, a1, a2, a3, b0, b1);
                MMA_F16(acc[jb * 2 + 1], a0, a1, a2, a3, b2, b3);
            }
        }
    };

    load_stage(0); CP_COMMIT();
    load_stage(1); CP_COMMIT();
    load_stage(2); CP_COMMIT();
    for (int c = 0; c < NCHUNK; c++) {
        asm volatile("cp.async.wait_group 2;" ::: "memory");
        __syncthreads();
        compute_stage(c);
        __syncthreads();
        if (c + 3 < NCHUNK) load_stage(c + 3);
        CP_COMMIT();
    }

    float* pbase = g_part + ((size_t)kb * BB + m0) * DD;
    const int row = wm * 16 + (lane >> 2);
    const int cb  = wn * 128 + (lane & 3) * 2;
#pragma unroll
    for (int f = 0; f < 16; f++) {
        const int n = cb + f * 8;
        *reinterpret_cast<float2*>(pbase + (size_t)row * DD + n) =
            make_float2(acc[f][0], acc[f][1]);
        *reinterpret_cast<float2*>(pbase + (size_t)(row + 8) * DD + n) =
            make_float2(acc[f][2], acc[f][3]);
    }
}

// ==================== 3) finalize ====================
__global__ void finalize_kernel(const float* __restrict__ E) {
    const int b = blockIdx.x;
    const int t = threadIdx.x;
    const int lab  = g_labels_s[b];
    const int node = g_idx_s[b];
    float v[4];
    if (lab) {
        float inv = 1.0f / g_rsumF[g_perm[b]];
        v[0] = v[1] = v[2] = v[3] = 0.f;
#pragma unroll
        for (int kb = 0; kb < KSPLIT; kb++) {
            float4 p = *reinterpret_cast<const float4*>(
                g_part + ((size_t)kb * BB + b) * DD + t * 4);
            v[0] += p.x; v[1] += p.y; v[2] += p.z; v[3] += p.w;
        }
#pragma unroll
        for (int j = 0; j < 4; j++) v[j] *= inv;
    } else {
        float4 p = *reinterpret_cast<const float4*>(E + (size_t)node * DD + t * 4);
        v[0] = p.x; v[1] = p.y; v[2] = p.z; v[3] = p.w;
    }
    size_t o = (size_t)b * DD + t * 4;
#pragma unroll
    for (int j = 0; j < 4; j++) {
        __nv_bfloat16 hi = __float2bfloat16_rn(v[j]);
        __nv_bfloat16 lo = __float2bfloat16_rn(v[j] - __bfloat162float(hi));
        g_hHi[o + j] = hi;
        g_hLo[o + j] = lo;
    }
}

// ==================== 4) MLP layer (512 threads, 16 warps) ====================
__global__ void __launch_bounds__(512, 1) mlp_kernel(
    const __nv_bfloat16* __restrict__ inHi, const __nv_bfloat16* __restrict__ inLo,
    const __nv_bfloat16* __restrict__ WHi,  const __nv_bfloat16* __restrict__ WLo,
    const float* __restrict__ bias,
    __nv_bfloat16* __restrict__ outHi, __nv_bfloat16* __restrict__ outLo,
    float* __restrict__ outF) {
    const int i0 = blockIdx.x * 128;
    const int o0 = blockIdx.y * 64;
    extern __shared__ __align__(1024) char smem[];
    const uint32_t sb = smem_u32(smem);
    const int t = threadIdx.x, lane = t & 31, wid = t >> 5;
    const int wm = wid & 7, wn = wid >> 3;   // 16 rows x 32 cols per warp
    const uint32_t sINhi = sb;
    const uint32_t sINlo = sb + MLP_IN_PL;
    const uint32_t sWhi  = sb + 2 * MLP_IN_PL;
    const uint32_t sWlo  = sWhi + MLP_W_PL;

    auto load_half = [&](int h) {
#pragma unroll
        for (int i = 0; i < 4; i++) {
            int g = t + 512 * i;
            int m = g >> 4, s = (g & 15) + h * 16;
            uint32_t off = m * 512 + (uint32_t)((s * 16) ^ ((m & 7) << 4));
            CP16(sINhi + off, inHi + (size_t)(i0 + m) * DD + s * 8);
            CP16(sINlo + off, inLo + (size_t)(i0 + m) * DD + s * 8);
        }
#pragma unroll
        for (int i = 0; i < 2; i++) {
            int g = t + 512 * i;
            int n = g >> 4, s = (g & 15) + h * 16;
            uint32_t off = n * 512 + (uint32_t)((s * 16) ^ ((n & 7) << 4));
            CP16(sWhi + off, WHi + (size_t)(o0 + n) * DD + s * 8);
            CP16(sWlo + off, WLo + (size_t)(o0 + n) * DD + s * 8);
        }
    };

    float acc[4][4];
#pragma unroll
    for (int f = 0; f < 4; f++)
#pragma unroll
        for (int r = 0; r < 4; r++) acc[f][r] = 0.f;

    auto comp_half = [&](int h) {
        const int q = lane >> 3, l7 = lane & 7;
#pragma unroll
        for (int ksl = 0; ksl < 8; ksl++) {
            const int ks = h * 8 + ksl;
            uint32_t ah[4], al[4];
            {
                const int m  = wm * 16 + (q & 1) * 8 + l7;
                const int kB = ks * 32 + (q >> 1) * 16;
                const uint32_t off = m * 512 + (uint32_t)(kB ^ ((m & 7) << 4));
                LDSM_X4(ah[0], ah[1], ah[2], ah[3], sINhi + off);
                LDSM_X4(al[0], al[1], al[2], al[3], sINlo + off);
            }
            uint32_t bh[2][4], bl[2][4];
#pragma unroll
            for (int nn = 0; nn < 2; nn++) {
                const int n  = wn * 32 + nn * 16 + (q >> 1) * 8 + l7;
                const int kB = ks * 32 + (q & 1) * 16;
                const uint32_t off = n * 512 + (uint32_t)(kB ^ ((n & 7) << 4));
                LDSM_X4(bh[nn][0], bh[nn][1], bh[nn][2], bh[nn][3], sWhi + off);
                LDSM_X4(bl[nn][0], bl[nn][1], bl[nn][2], bl[nn][3], sWlo + off);
            }
#pragma unroll
            for (int nn = 0; nn < 2; nn++) {
                float* d0 = acc[nn * 2];
                float* d1 = acc[nn * 2 + 1];
                MMA_BF16(d0, ah[0], ah[1], ah[2], ah[3], bh[nn][0], bh[nn][1]);
                MMA_BF16(d0, al[0], al[1], al[2], al[3], bh[nn][0], bh[nn][1]);
                MMA_BF16(d0, ah[0], ah[1], ah[2], ah[3], bl[nn][0], bl[nn][1]);
                MMA_BF16(d1, ah[0], ah[1], ah[2], ah[3], bh[nn][2], bh[nn][3]);
                MMA_BF16(d1, al[0], al[1], al[2], al[3], bh[nn][2], bh[nn][3]);
                MMA_BF16(d1, ah[0], ah[1], ah[2], ah[3], bl[nn][2], bl[nn][3]);
            }
        }
    };

    load_half(0); CP_COMMIT();
    load_half(1); CP_COMMIT();
    asm volatile("cp.async.wait_group 1;" ::: "memory");
    __syncthreads();
    comp_half(0);
    asm volatile("cp.async.wait_group 0;" ::: "memory");
    __syncthreads();
    comp_half(1);

    const int row0 = i0 + wm * 16 + (lane >> 2);
#pragma unroll
    for (int f = 0; f < 4; f++) {
        const int col = o0 + wn * 32 + f * 8 + (lane & 3) * 2;
        const float b0 = bias[col], b1 = bias[col + 1];
        float y00 = fmaxf(acc[f][0] + b0, 0.f);
        float y01 = fmaxf(acc[f][1] + b1, 0.f);
        float y10 = fmaxf(acc[f][2] + b0, 0.f);
        float y11 = fmaxf(acc[f][3] + b1, 0.f);
        if (outF) {
            *reinterpret_cast<float2*>(outF + (size_t)row0 * DD + col) = make_float2(y00, y01);
            *reinterpret_cast<float2*>(outF + (size_t)(row0 + 8) * DD + col) = make_float2(y10, y11);
        } else {
            float y[4] = {y00, y01, y10, y11};
            __nv_bfloat16 hi[4], lo[4];
#pragma unroll
            for (int j = 0; j < 4; j++) {
                hi[j] = __float2bfloat16_rn(y[j]);
                lo[j] = __float2bfloat16_rn(y[j] - __bfloat162float(hi[j]));
            }
            *reinterpret_cast<__nv_bfloat162*>(outHi + (size_t)row0 * DD + col) = __halves2bfloat162(hi[0], hi[1]);
            *reinterpret_cast<__nv_bfloat162*>(outHi + (size_t)(row0 + 8) * DD + col) = __halves2bfloat162(hi[2], hi[3]);
            *reinterpret_cast<__nv_bfloat162*>(outLo + (size_t)row0 * DD + col) = __halves2bfloat162(lo[0], lo[1]);
            *reinterpret_cast<__nv_bfloat162*>(outLo + (size_t)(row0 + 8) * DD + col) = __halves2bfloat162(lo[2], lo[3]);
        }
    }
}

// ==================== launch ====================
extern "C" void kernel_launch(void* const* d_in, const int* in_sizes, int n_in,
                              void* d_out, int out_size) {
    const int*   labels = (const int*)d_in[0];
    const int*   nidx   = (const int*)d_in[1];
    const float* A      = (const float*)d_in[2];
    const float* E      = (const float*)d_in[3];
    const float* W      = (const float*)d_in[4];
    const float* bias   = (const float*)d_in[5];

    float* out        = (float*)d_out;
    float* out_labels = nullptr;
    float* out_h      = out;
    if (out_size >= BB * DD + BB) {
        out_labels = out;
        out_h      = out + BB;
    }

    __nv_bfloat16 *hHi, *hLo, *h2Hi, *h2Lo, *WHi, *WLo;
    cudaGetSymbolAddress((void**)&hHi,  g_hHi);
    cudaGetSymbolAddress((void**)&hLo,  g_hLo);
    cudaGetSymbolAddress((void**)&h2Hi, g_h2Hi);
    cudaGetSymbolAddress((void**)&h2Lo, g_h2Lo);
    cudaGetSymbolAddress((void**)&WHi,  g_WHi);
    cudaGetSymbolAddress((void**)&WLo,  g_WLo);

    cudaFuncSetAttribute(gemm1_kernel,
                         cudaFuncAttributeMaxDynamicSharedMemorySize, GEMM_SMEM);
    cudaFuncSetAttribute(mlp_kernel,
                         cudaFuncAttributeMaxDynamicSharedMemorySize, MLP_SMEM);

    prep_kernel<<<PREP_GRID, 256>>>(labels, nidx, A, E, W, out_labels);
    gemm1_kernel<<<dim3(KSPLIT, BB / MT), 256, GEMM_SMEM>>>();
    finalize_kernel<<<BB, 64>>>(E);
    mlp_kernel<<<dim3(BB / 128, DD / 64), 512, MLP_SMEM>>>(
        hHi, hLo, WHi, WLo, bias, h2Hi, h2Lo, nullptr);
    mlp_kernel<<<dim3(BB / 128, DD / 64), 512, MLP_SMEM>>>(
        h2Hi, h2Lo, WHi + DD * DD, WLo + DD * DD, bias + DD, hHi, hLo, nullptr);
    mlp_kernel<<<dim3(BB / 128, DD / 64), 512, MLP_SMEM>>>(
        hHi, hLo, WHi + 2 * DD * DD, WLo + 2 * DD * DD, bias + 2 * DD,
        nullptr, nullptr, out_h);
}